// round 5
// baseline (speedup 1.0000x reference)
#include <cuda_runtime.h>
#include <cuda_bf16.h>
#include <cstdint>

#define K_COMP   8
#define L_LAT    64
#define D_DATA   256
#define N_ROWS   16384
#define B_ROWS   2048
#define ENC_OUT  1536   // 3*K*L
#define DEC_OUT  6144   // 3*K*D
#define NB_SAMP  4096   // (16384*64)/256
#define ROWS_PB  16
#define NB_DEC   (N_ROWS / ROWS_PB)   // 1024
#define WPK_N    (3 * 32 * 2048)      // 196608 packed words

__device__ float    g_pred_e[B_ROWS * ENC_OUT];   // 12.6 MB
__device__ float    g_h[N_ROWS * L_LAT];          // 4 MB
__device__ uint32_t g_wpk[WPK_N];                 // W_d bf16, l-pairs packed
__device__ float    g_partB[NB_SAMP];
__device__ float    g_partC[NB_DEC];

// ---- packed helpers ------------------------------------------------------
typedef unsigned long long u64;

__device__ __forceinline__ u64 pack2(float lo, float hi) {
    u64 o; asm("mov.b64 %0, {%1, %2};" : "=l"(o) : "f"(lo), "f"(hi)); return o;
}
__device__ __forceinline__ u64 bcast2(float v) {
    u64 o; asm("mov.b64 %0, {%1, %1};" : "=l"(o) : "f"(v)); return o;
}
__device__ __forceinline__ void unpack2(u64 d, float& lo, float& hi) {
    asm("mov.b64 {%0, %1}, %2;" : "=f"(lo), "=f"(hi) : "l"(d));
}
__device__ __forceinline__ void fma2(u64& d, u64 a, u64 b) {
    asm("fma.rn.f32x2 %0, %1, %2, %0;" : "+l"(d) : "l"(a), "l"(b));
}
__device__ __forceinline__ uint32_t bf16x2_pack(float hi, float lo) {
    uint32_t o; asm("cvt.rn.bf16x2.f32 %0, %1, %2;" : "=r"(o) : "f"(hi), "f"(lo)); return o;
}
__device__ __forceinline__ uint32_t hfma2(uint32_t a, uint32_t b, uint32_t c) {
    uint32_t d; asm("fma.rn.bf16x2 %0, %1, %2, %3;" : "=r"(d) : "r"(a), "r"(b), "r"(c));
    return d;
}
__device__ __forceinline__ float bf_lo(uint32_t v) { return __uint_as_float(v << 16); }
__device__ __forceinline__ float bf_hi(uint32_t v) { return __uint_as_float(v & 0xFFFF0000u); }

__device__ __forceinline__ float block_reduce_256(float v) {
    __shared__ float red[8];
    int lane = threadIdx.x & 31, wid = threadIdx.x >> 5;
    #pragma unroll
    for (int o = 16; o > 0; o >>= 1) v += __shfl_down_sync(0xffffffffu, v, o);
    if (lane == 0) red[wid] = v;
    __syncthreads();
    if (wid == 0) {
        v = (lane < 8) ? red[lane] : 0.0f;
        #pragma unroll
        for (int o = 4; o > 0; o >>= 1) v += __shfl_down_sync(0xffffffffu, v, o);
    }
    return v;   // valid on thread 0
}

// ---------------------------------------------------------------------------
// Pack W_d -> bf16 l-pairs: g_wpk[(t*32+l2)*2048 + col] =
//   {bf16(Wd[2*l2+1][t*2048+col]) , bf16(Wd[2*l2][t*2048+col])}
// ---------------------------------------------------------------------------
__global__ __launch_bounds__(256) void prep_w(const float* __restrict__ Wd)
{
    int i = blockIdx.x * 256 + threadIdx.x;   // < 196608
    int col = i & 2047;
    int tl = i >> 11;            // t*32 + l2
    int t = tl >> 5, l2 = tl & 31;
    int base = t * 2048 + col;
    float w0 = Wd[(2 * l2) * DEC_OUT + base];
    float w1 = Wd[(2 * l2 + 1) * DEC_OUT + base];
    g_wpk[i] = bf16x2_pack(w1, w0);
}

// ---------------------------------------------------------------------------
// Encoder GEMM (fp32 FFMA2): pred_e(2048,1536) = x @ W_e + b_e
// ---------------------------------------------------------------------------
__global__ __launch_bounds__(256) void enc_gemm(const float* __restrict__ x,
                                                const float* __restrict__ We,
                                                const float* __restrict__ be)
{
    __shared__ float As[16][64];
    __shared__ float Bs[16][64];
    const int tid = threadIdx.x;
    const int tx = tid & 15, ty = tid >> 4;
    const int bm = blockIdx.y * 64, bn = blockIdx.x * 64;

    u64 acc[4][2];
    #pragma unroll
    for (int i = 0; i < 4; i++) { acc[i][0] = pack2(0.f, 0.f); acc[i][1] = pack2(0.f, 0.f); }

    const int am = tid >> 2;
    const int ak = (tid & 3) * 4;
    const int bk = tid >> 6;
    const int bnn = tid & 63;

    for (int kt = 0; kt < 256; kt += 16) {
        float4 xa = *reinterpret_cast<const float4*>(x + (bm + am) * D_DATA + kt + ak);
        As[ak + 0][am] = xa.x;
        As[ak + 1][am] = xa.y;
        As[ak + 2][am] = xa.z;
        As[ak + 3][am] = xa.w;
        #pragma unroll
        for (int i = 0; i < 4; i++)
            Bs[bk + i * 4][bnn] = We[(kt + bk + i * 4) * ENC_OUT + bn + bnn];
        __syncthreads();

        #pragma unroll
        for (int kk = 0; kk < 16; kk++) {
            float4 av = *reinterpret_cast<const float4*>(&As[kk][ty * 4]);
            u64 b01 = *reinterpret_cast<const u64*>(&Bs[kk][tx * 4]);
            u64 b23 = *reinterpret_cast<const u64*>(&Bs[kk][tx * 4 + 2]);
            u64 a0 = bcast2(av.x), a1 = bcast2(av.y), a2 = bcast2(av.z), a3 = bcast2(av.w);
            fma2(acc[0][0], a0, b01); fma2(acc[0][1], a0, b23);
            fma2(acc[1][0], a1, b01); fma2(acc[1][1], a1, b23);
            fma2(acc[2][0], a2, b01); fma2(acc[2][1], a2, b23);
            fma2(acc[3][0], a3, b01); fma2(acc[3][1], a3, b23);
        }
        __syncthreads();
    }

    #pragma unroll
    for (int i = 0; i < 4; i++) {
        float v0, v1, v2, v3;
        unpack2(acc[i][0], v0, v1);
        unpack2(acc[i][1], v2, v3);
        int col = bn + tx * 4;
        float* outp = g_pred_e + (bm + ty * 4 + i) * ENC_OUT + col;
        outp[0] = v0 + be[col + 0];
        outp[1] = v1 + be[col + 1];
        outp[2] = v2 + be[col + 2];
        outp[3] = v3 + be[col + 3];
    }
}

// ---------------------------------------------------------------------------
// Sampling + h + (L_q - L_e) partials. One thread per (n, l). fp32 exact.
// ---------------------------------------------------------------------------
__global__ __launch_bounds__(256) void sample_k(const float* __restrict__ ue,
                                                const float* __restrict__ rr)
{
    const int g = blockIdx.x * 256 + threadIdx.x;
    const int n = g >> 6, l = g & 63;
    const float* row = g_pred_e + (n & (B_ROWS - 1)) * ENC_OUT;

    float a[K_COMP], e[K_COMP];
    float amax = -1e30f;
    #pragma unroll
    for (int k = 0; k < K_COMP; k++) {
        a[k] = row[1024 + k * 64 + l];
        amax = fmaxf(amax, a[k]);
    }
    float s = 0.0f;
    #pragma unroll
    for (int k = 0; k < K_COMP; k++) { e[k] = __expf(a[k] - amax); s += e[k]; }
    const float lse_a = amax + __logf(s);
    const float inv = 1.0f / s;

    const float rv = rr[n * 64 + l];
    float c = 0.0f;
    int idx = 0;
    #pragma unroll
    for (int k = 0; k < K_COMP; k++) {
        c += e[k] * inv;
        idx += (rv > c) ? 1 : 0;
    }
    if (idx > K_COMP - 1) idx = K_COMP - 1;

    const float msel = row[idx * 64 + l];
    const float psel = row[512 + idx * 64 + l];
    const float hv = msel + __expf(-0.5f * psel) * ue[n * 64 + l];
    g_h[n * 64 + l] = hv;

    float st = 0.0f;
    #pragma unroll
    for (int k = 0; k < K_COMP; k++) {
        float m = row[k * 64 + l];
        float p = row[512 + k * 64 + l];
        float dd = hv - m;
        st += __expf(a[k] + 0.5f * p - 0.5f * __expf(p) * dd * dd);
    }
    const float lse_s = __logf(st) - lse_a;

    float v = -0.5f * hv * hv - lse_s;
    v = block_reduce_256(v);
    if (threadIdx.x == 0) g_partB[blockIdx.x] = v;
}

// ---------------------------------------------------------------------------
// Fused decoder GEMM + mixture likelihood: bf16 HFMA2.
// 3 CTAs/SM (sums in smem, regs <= 85). 16 rows = 8 bf16x2 pairs per block.
// h pairs fetched as LDS.64 (both l-values of an l2 step in one load).
// ---------------------------------------------------------------------------
__global__ __launch_bounds__(256, 3) void dec_k(const float* __restrict__ x,
                                                const float* __restrict__ bd)
{
    __shared__ uint2 hp2[32][8];     // [l2][pair]: .x = l=2*l2 pair, .y = l=2*l2+1 pair
    __shared__ float st[ROWS_PB][256];
    __shared__ float sa[ROWS_PB][256];

    const int d = threadIdx.x;
    const int row0 = blockIdx.x * ROWS_PB;

    // stage h pairs (256 entries, one per thread)
    {
        int l2 = threadIdx.x >> 3, p = threadIdx.x & 7;
        const float* h0p = g_h + (row0 + 2 * p) * 64 + 2 * l2;
        const float* h1p = g_h + (row0 + 2 * p + 1) * 64 + 2 * l2;
        float2 ha = *reinterpret_cast<const float2*>(h0p);
        float2 hb = *reinterpret_cast<const float2*>(h1p);
        uint2 v;
        v.x = bf16x2_pack(hb.x, ha.x);   // l = 2*l2
        v.y = bf16x2_pack(hb.y, ha.y);   // l = 2*l2+1
        hp2[l2][p] = v;
    }
    #pragma unroll
    for (int r = 0; r < ROWS_PB; r++) { st[r][d] = 0.0f; sa[r][d] = 0.0f; }
    __syncthreads();

    float xv[ROWS_PB];
    const int xrow = row0 & (B_ROWS - 1);
    #pragma unroll
    for (int r = 0; r < ROWS_PB; r++)
        xv[r] = x[(xrow + r) * D_DATA + d];

    for (int k = 0; k < K_COMP; k++) {
        uint32_t am[8], ap[8], aa[8];
        #pragma unroll
        for (int p = 0; p < 8; p++) { am[p] = 0u; ap[p] = 0u; aa[p] = 0u; }

        const uint32_t* w = g_wpk + k * 256 + d;
        #pragma unroll 4
        for (int l2 = 0; l2 < 32; l2++) {
            uint32_t vm = w[l2 * 2048];
            uint32_t vp = w[32 * 2048 + l2 * 2048];
            uint32_t va = w[64 * 2048 + l2 * 2048];
            uint32_t bm0 = __byte_perm(vm, vm, 0x1010), bm1 = __byte_perm(vm, vm, 0x3232);
            uint32_t bp0 = __byte_perm(vp, vp, 0x1010), bp1 = __byte_perm(vp, vp, 0x3232);
            uint32_t ba0 = __byte_perm(va, va, 0x1010), ba1 = __byte_perm(va, va, 0x3232);
            #pragma unroll
            for (int p = 0; p < 8; p++) {
                uint2 h = hp2[l2][p];
                am[p] = hfma2(h.x, bm0, am[p]);
                ap[p] = hfma2(h.x, bp0, ap[p]);
                aa[p] = hfma2(h.x, ba0, aa[p]);
                am[p] = hfma2(h.y, bm1, am[p]);
                ap[p] = hfma2(h.y, bp1, ap[p]);
                aa[p] = hfma2(h.y, ba1, aa[p]);
            }
        }

        const float bm = bd[k * D_DATA + d];
        const float bp = bd[2048 + k * D_DATA + d];
        const float ba = bd[4096 + k * D_DATA + d];
        #pragma unroll
        for (int p = 0; p < 8; p++) {
            {
                float m = bf_lo(am[p]) + bm, pv = bf_lo(ap[p]) + bp, av = bf_lo(aa[p]) + ba;
                float dd = xv[2 * p] - m;
                float t = av + 0.5f * pv - 0.5f * __expf(pv) * dd * dd;
                st[2 * p][d] += __expf(t);
                sa[2 * p][d] += __expf(av);
            }
            {
                float m = bf_hi(am[p]) + bm, pv = bf_hi(ap[p]) + bp, av = bf_hi(aa[p]) + ba;
                float dd = xv[2 * p + 1] - m;
                float t = av + 0.5f * pv - 0.5f * __expf(pv) * dd * dd;
                st[2 * p + 1][d] += __expf(t);
                sa[2 * p + 1][d] += __expf(av);
            }
        }
    }

    float part = 0.0f;
    #pragma unroll
    for (int r = 0; r < ROWS_PB; r++)
        part += __logf(st[r][d]) - __logf(sa[r][d]);

    __syncthreads();
    part = block_reduce_256(part);
    if (threadIdx.x == 0) g_partC[blockIdx.x] = part;
}

// ---------------------------------------------------------------------------
// Final reduction: out = -( (PB + PC)/N + c2 ),  c2 = -0.5*D*log(2*pi)
// ---------------------------------------------------------------------------
__global__ __launch_bounds__(1024) void final_k(float* __restrict__ out)
{
    __shared__ float red[32];
    float s = 0.0f;
    const float4* pb = reinterpret_cast<const float4*>(g_partB);
    for (int i = threadIdx.x; i < NB_SAMP / 4; i += 1024) {
        float4 v = pb[i]; s += (v.x + v.y) + (v.z + v.w);
    }
    const float4* pc = reinterpret_cast<const float4*>(g_partC);
    for (int i = threadIdx.x; i < NB_DEC / 4; i += 1024) {
        float4 v = pc[i]; s += (v.x + v.y) + (v.z + v.w);
    }
    int lane = threadIdx.x & 31, wid = threadIdx.x >> 5;
    #pragma unroll
    for (int o = 16; o > 0; o >>= 1) s += __shfl_down_sync(0xffffffffu, s, o);
    if (lane == 0) red[wid] = s;
    __syncthreads();
    if (wid == 0) {
        s = red[lane];
        #pragma unroll
        for (int o = 16; o > 0; o >>= 1) s += __shfl_down_sync(0xffffffffu, s, o);
        if (lane == 0) {
            const float c2 = -0.5f * 256.0f * 1.8378770664093453f;
            out[0] = -(s / (float)N_ROWS + c2);
        }
    }
}

extern "C" void kernel_launch(void* const* d_in, const int* in_sizes, int n_in,
                              void* d_out, int out_size) {
    const float* x  = (const float*)d_in[0];
    const float* We = (const float*)d_in[1];
    const float* be = (const float*)d_in[2];
    const float* Wd = (const float*)d_in[3];
    const float* bd = (const float*)d_in[4];
    const float* ue = (const float*)d_in[5];
    const float* rr = (const float*)d_in[6];
    float* out = (float*)d_out;

    prep_w<<<WPK_N / 256, 256>>>(Wd);
    dim3 ge(ENC_OUT / 64, B_ROWS / 64);
    enc_gemm<<<ge, 256>>>(x, We, be);
    sample_k<<<NB_SAMP, 256>>>(ue, rr);
    dec_k<<<NB_DEC, 256>>>(x, bd);
    final_k<<<1, 1024>>>(out);
}

// round 6
// speedup vs baseline: 1.7643x; 1.7643x over previous
#include <cuda_runtime.h>
#include <cuda_bf16.h>
#include <cstdint>

#define K_COMP   8
#define L_LAT    64
#define D_DATA   256
#define N_ROWS   16384
#define B_ROWS   2048
#define ENC_OUT  1536   // 3*K*L
#define DEC_OUT  6144   // 3*K*D
#define NB_SAMP  4096   // (16384*64)/256
#define NB_DEC   256    // 16384/64
#define WT_N     196608 // 6144 cols * 32 u32 (64 bf16 k) packed

__device__ float    g_pred_e[B_ROWS * ENC_OUT];   // 12.6 MB
__device__ float    g_h[N_ROWS * L_LAT];          // 4 MB
__device__ uint32_t g_wT[WT_N];                   // W_d^T bf16 tiles [dc][kc][t][n][k]
__device__ float    g_partB[NB_SAMP];
__device__ float    g_partC[NB_DEC];

typedef unsigned long long u64;

// ---- helpers -------------------------------------------------------------
__device__ __forceinline__ u64 pack2(float lo, float hi) {
    u64 o; asm("mov.b64 %0, {%1, %2};" : "=l"(o) : "f"(lo), "f"(hi)); return o;
}
__device__ __forceinline__ u64 bcast2(float v) {
    u64 o; asm("mov.b64 %0, {%1, %1};" : "=l"(o) : "f"(v)); return o;
}
__device__ __forceinline__ void unpack2(u64 d, float& lo, float& hi) {
    asm("mov.b64 {%0, %1}, %2;" : "=f"(lo), "=f"(hi) : "l"(d));
}
__device__ __forceinline__ void fma2(u64& d, u64 a, u64 b) {
    asm("fma.rn.f32x2 %0, %1, %2, %0;" : "+l"(d) : "l"(a), "l"(b));
}
__device__ __forceinline__ uint32_t bf16x2_pack(float hi, float lo) {
    uint32_t o; asm("cvt.rn.bf16x2.f32 %0, %1, %2;" : "=r"(o) : "f"(hi), "f"(lo)); return o;
}
__device__ __forceinline__ uint32_t smem_u32(const void* p) {
    uint32_t a;
    asm("{ .reg .u64 t; cvta.to.shared.u64 t, %1; cvt.u32.u64 %0, t; }" : "=r"(a) : "l"(p));
    return a;
}
#define SW128(b) ((b) ^ (((b) >> 3) & 0x70))

#define LDMATRIX_X4(r0, r1, r2, r3, addr)                                     \
    asm volatile("ldmatrix.sync.aligned.m8n8.x4.shared.b16 {%0,%1,%2,%3}, [%4];" \
        : "=r"(r0), "=r"(r1), "=r"(r2), "=r"(r3) : "r"(addr))

#define MMA_BF16(c, a0, a1, a2, a3, b0, b1)                                   \
    asm volatile("mma.sync.aligned.m16n8k16.row.col.f32.bf16.bf16.f32 "       \
        "{%0,%1,%2,%3}, {%4,%5,%6,%7}, {%8,%9}, {%0,%1,%2,%3};"               \
        : "+f"((c)[0]), "+f"((c)[1]), "+f"((c)[2]), "+f"((c)[3])              \
        : "r"(a0), "r"(a1), "r"(a2), "r"(a3), "r"(b0), "r"(b1))

#define CP_ASYNC16(saddr, gaddr)                                              \
    asm volatile("cp.async.cg.shared.global [%0], [%1], 16;" :: "r"(saddr), "l"(gaddr))
#define CP_COMMIT() asm volatile("cp.async.commit_group;")
#define CP_WAIT(n)  asm volatile("cp.async.wait_group %0;" :: "n"(n))

__device__ __forceinline__ float block_reduce_256(float v) {
    __shared__ float red[8];
    int lane = threadIdx.x & 31, wid = threadIdx.x >> 5;
    #pragma unroll
    for (int o = 16; o > 0; o >>= 1) v += __shfl_down_sync(0xffffffffu, v, o);
    if (lane == 0) red[wid] = v;
    __syncthreads();
    if (wid == 0) {
        v = (lane < 8) ? red[lane] : 0.0f;
        #pragma unroll
        for (int o = 4; o > 0; o >>= 1) v += __shfl_down_sync(0xffffffffu, v, o);
    }
    return v;
}

// ---------------------------------------------------------------------------
// Pack W_d -> bf16 tiles: g_wT[((dc*8+kc)*3+t)*256 + n*32 + kp] =
//   {bf16(Wd[2kp+1][col]), bf16(Wd[2kp][col])}, col = t*2048+kc*256+dc*8+n
// ---------------------------------------------------------------------------
__global__ __launch_bounds__(256) void prep_w(const float* __restrict__ Wd)
{
    int i = blockIdx.x * 256 + threadIdx.x;   // < 196608
    int kp = i & 31;
    int n  = (i >> 5) & 7;
    int tile = i >> 8;
    int t = tile % 3;
    int q = tile / 3;
    int kc = q & 7, dc = q >> 3;
    int col = t * 2048 + kc * 256 + dc * 8 + n;
    float w0 = Wd[(2 * kp) * DEC_OUT + col];
    float w1 = Wd[(2 * kp + 1) * DEC_OUT + col];
    g_wT[i] = bf16x2_pack(w1, w0);
}

// ---------------------------------------------------------------------------
// Encoder GEMM (fp32 FFMA2): pred_e(2048,1536) = x @ W_e + b_e
// ---------------------------------------------------------------------------
__global__ __launch_bounds__(256) void enc_gemm(const float* __restrict__ x,
                                                const float* __restrict__ We,
                                                const float* __restrict__ be)
{
    __shared__ float As[16][64];
    __shared__ float Bs[16][64];
    const int tid = threadIdx.x;
    const int tx = tid & 15, ty = tid >> 4;
    const int bm = blockIdx.y * 64, bn = blockIdx.x * 64;

    u64 acc[4][2];
    #pragma unroll
    for (int i = 0; i < 4; i++) { acc[i][0] = pack2(0.f, 0.f); acc[i][1] = pack2(0.f, 0.f); }

    const int am = tid >> 2;
    const int ak = (tid & 3) * 4;
    const int bk = tid >> 6;
    const int bnn = tid & 63;

    for (int kt = 0; kt < 256; kt += 16) {
        float4 xa = *reinterpret_cast<const float4*>(x + (bm + am) * D_DATA + kt + ak);
        As[ak + 0][am] = xa.x;
        As[ak + 1][am] = xa.y;
        As[ak + 2][am] = xa.z;
        As[ak + 3][am] = xa.w;
        #pragma unroll
        for (int i = 0; i < 4; i++)
            Bs[bk + i * 4][bnn] = We[(kt + bk + i * 4) * ENC_OUT + bn + bnn];
        __syncthreads();

        #pragma unroll
        for (int kk = 0; kk < 16; kk++) {
            float4 av = *reinterpret_cast<const float4*>(&As[kk][ty * 4]);
            u64 b01 = *reinterpret_cast<const u64*>(&Bs[kk][tx * 4]);
            u64 b23 = *reinterpret_cast<const u64*>(&Bs[kk][tx * 4 + 2]);
            u64 a0 = bcast2(av.x), a1 = bcast2(av.y), a2 = bcast2(av.z), a3 = bcast2(av.w);
            fma2(acc[0][0], a0, b01); fma2(acc[0][1], a0, b23);
            fma2(acc[1][0], a1, b01); fma2(acc[1][1], a1, b23);
            fma2(acc[2][0], a2, b01); fma2(acc[2][1], a2, b23);
            fma2(acc[3][0], a3, b01); fma2(acc[3][1], a3, b23);
        }
        __syncthreads();
    }

    #pragma unroll
    for (int i = 0; i < 4; i++) {
        float v0, v1, v2, v3;
        unpack2(acc[i][0], v0, v1);
        unpack2(acc[i][1], v2, v3);
        int col = bn + tx * 4;
        float* outp = g_pred_e + (bm + ty * 4 + i) * ENC_OUT + col;
        outp[0] = v0 + be[col + 0];
        outp[1] = v1 + be[col + 1];
        outp[2] = v2 + be[col + 2];
        outp[3] = v3 + be[col + 3];
    }
}

// ---------------------------------------------------------------------------
// Sampling + h + (L_q - L_e) partials. One thread per (n, l). fp32 exact.
// ---------------------------------------------------------------------------
__global__ __launch_bounds__(256) void sample_k(const float* __restrict__ ue,
                                                const float* __restrict__ rr)
{
    const int g = blockIdx.x * 256 + threadIdx.x;
    const int n = g >> 6, l = g & 63;
    const float* row = g_pred_e + (n & (B_ROWS - 1)) * ENC_OUT;

    float a[K_COMP], e[K_COMP];
    float amax = -1e30f;
    #pragma unroll
    for (int k = 0; k < K_COMP; k++) {
        a[k] = row[1024 + k * 64 + l];
        amax = fmaxf(amax, a[k]);
    }
    float s = 0.0f;
    #pragma unroll
    for (int k = 0; k < K_COMP; k++) { e[k] = __expf(a[k] - amax); s += e[k]; }
    const float lse_a = amax + __logf(s);
    const float inv = 1.0f / s;

    const float rv = rr[n * 64 + l];
    float c = 0.0f;
    int idx = 0;
    #pragma unroll
    for (int k = 0; k < K_COMP; k++) {
        c += e[k] * inv;
        idx += (rv > c) ? 1 : 0;
    }
    if (idx > K_COMP - 1) idx = K_COMP - 1;

    const float msel = row[idx * 64 + l];
    const float psel = row[512 + idx * 64 + l];
    const float hv = msel + __expf(-0.5f * psel) * ue[n * 64 + l];
    g_h[n * 64 + l] = hv;

    float st = 0.0f;
    #pragma unroll
    for (int k = 0; k < K_COMP; k++) {
        float m = row[k * 64 + l];
        float p = row[512 + k * 64 + l];
        float dd = hv - m;
        st += __expf(a[k] + 0.5f * p - 0.5f * __expf(p) * dd * dd);
    }
    const float lse_s = __logf(st) - lse_a;

    float v = -0.5f * hv * hv - lse_s;
    v = block_reduce_256(v);
    if (threadIdx.x == 0) g_partB[blockIdx.x] = v;
}

// ---------------------------------------------------------------------------
// Decoder: tensor-core (mma.sync bf16) GEMM + fused mixture epilogue.
// Grid 256, 128 threads (4 warps x m16). M-tile 64 rows, d-chunks of 8.
// Smem: B double buffer 2x24KB | h tile 8KB | bd 24KB  = 80KB dynamic.
// ---------------------------------------------------------------------------
__global__ void dec_k(const float* __restrict__ x,
                      const float* __restrict__ bd)
{
    extern __shared__ uint32_t dsm[];
    uint32_t* bufB = dsm;              // [0, 12288) u32 : two 24KB buffers
    uint32_t* hsm  = dsm + 12288;      // [12288, 14336) : h tile 64x64 bf16
    float*    bds  = (float*)(dsm + 14336);  // 6144 floats

    const int tid  = threadIdx.x;
    const int lane = tid & 31;
    const int warp = tid >> 5;
    const int row0 = blockIdx.x * 64;

    const uint32_t sb_bufB = smem_u32(bufB);
    const uint32_t sb_h    = smem_u32(hsm);

    // stage bd (6144 floats, 128 threads x 12 x float4)
    {
        const float4* src = reinterpret_cast<const float4*>(bd);
        float4* dst = reinterpret_cast<float4*>(bds);
        #pragma unroll
        for (int j = 0; j < 12; j++) dst[tid + j * 128] = src[tid + j * 128];
    }
    // stage h tile: row = tid>>1, k-half = tid&1 (32 k values -> 16 u32), SW128
    {
        int r = tid >> 1, kh = tid & 1;
        const float* hp = g_h + (row0 + r) * 64 + kh * 32;
        #pragma unroll
        for (int j = 0; j < 16; j++) {
            float2 v = *reinterpret_cast<const float2*>(hp + 2 * j);
            uint32_t off = r * 128 + (kh * 32 + 2 * j) * 2;
            hsm[SW128(off) >> 2] = bf16x2_pack(v.y, v.x);
        }
    }
    __syncthreads();

    // A fragments: 4 k-steps, held for the whole kernel
    uint32_t afr[4][4];
    {
        const int m0 = warp * 16;
        #pragma unroll
        for (int s = 0; s < 4; s++) {
            int r = m0 + ((lane >> 3) & 1) * 8 + (lane & 7);
            uint32_t off = r * 128 + s * 32 + ((lane >> 4) & 1) * 16;
            uint32_t addr = sb_h + SW128(off);
            LDMATRIX_X4(afr[s][0], afr[s][1], afr[s][2], afr[s][3], addr);
        }
    }

    // prefetch d-chunk 0
    {
        const uint32_t* gsrc = g_wT;
        #pragma unroll
        for (int j = 0; j < 12; j++) {
            int c = tid + j * 128;
            uint32_t off = (c & 63) * 16;
            uint32_t so = (uint32_t)(c >> 6) * 1024 + SW128(off);
            CP_ASYNC16(sb_bufB + so, gsrc + c * 4);
        }
        CP_COMMIT();
    }

    // epilogue geometry
    const int g8  = lane >> 2;
    const int c2  = (lane & 3) * 2;
    const int xr0 = (row0 + warp * 16 + g8) & (B_ROWS - 1);
    const int xr1 = (row0 + warp * 16 + g8 + 8) & (B_ROWS - 1);

    float part = 0.0f;

    for (int dc = 0; dc < 32; dc++) {
        const uint32_t curB = sb_bufB + (dc & 1) * 24576;

        if (dc < 31) {
            const uint32_t* gsrc = g_wT + (dc + 1) * 6144;
            const uint32_t nxtB = sb_bufB + ((dc + 1) & 1) * 24576;
            #pragma unroll
            for (int j = 0; j < 12; j++) {
                int c = tid + j * 128;
                uint32_t off = (c & 63) * 16;
                uint32_t so = (uint32_t)(c >> 6) * 1024 + SW128(off);
                CP_ASYNC16(nxtB + so, gsrc + c * 4);
            }
            CP_COMMIT();
            CP_WAIT(1);
        } else {
            CP_WAIT(0);
        }
        __syncthreads();

        const int d0 = dc * 8 + c2;
        float2 x0 = *reinterpret_cast<const float2*>(x + xr0 * D_DATA + d0);
        float2 x1 = *reinterpret_cast<const float2*>(x + xr1 * D_DATA + d0);

        float s_t[4] = {0.f, 0.f, 0.f, 0.f};
        float s_a[4] = {0.f, 0.f, 0.f, 0.f};

        #pragma unroll
        for (int kc = 0; kc < K_COMP; kc++) {
            float cm[4] = {0.f, 0.f, 0.f, 0.f};
            float cp_[4] = {0.f, 0.f, 0.f, 0.f};
            float ca[4] = {0.f, 0.f, 0.f, 0.f};

            const uint32_t tb = curB + kc * 3072;
            const uint32_t boff = (uint32_t)(lane & 7) * 128 + (uint32_t)(lane >> 3) * 16;
            #pragma unroll
            for (int s2 = 0; s2 < 2; s2++) {
                uint32_t b0, b1, b2, b3;
                uint32_t a_sw = SW128(boff + s2 * 64);
                // type 0 (m)
                LDMATRIX_X4(b0, b1, b2, b3, tb + a_sw);
                MMA_BF16(cm, afr[2*s2][0], afr[2*s2][1], afr[2*s2][2], afr[2*s2][3], b0, b1);
                MMA_BF16(cm, afr[2*s2+1][0], afr[2*s2+1][1], afr[2*s2+1][2], afr[2*s2+1][3], b2, b3);
                // type 1 (logp)
                LDMATRIX_X4(b0, b1, b2, b3, tb + 1024 + a_sw);
                MMA_BF16(cp_, afr[2*s2][0], afr[2*s2][1], afr[2*s2][2], afr[2*s2][3], b0, b1);
                MMA_BF16(cp_, afr[2*s2+1][0], afr[2*s2+1][1], afr[2*s2+1][2], afr[2*s2+1][3], b2, b3);
                // type 2 (loga)
                LDMATRIX_X4(b0, b1, b2, b3, tb + 2048 + a_sw);
                MMA_BF16(ca, afr[2*s2][0], afr[2*s2][1], afr[2*s2][2], afr[2*s2][3], b0, b1);
                MMA_BF16(ca, afr[2*s2+1][0], afr[2*s2+1][1], afr[2*s2+1][2], afr[2*s2+1][3], b2, b3);
            }

            const int bi = kc * 256 + d0;
            float2 bm2 = *reinterpret_cast<const float2*>(bds + bi);
            float2 bp2 = *reinterpret_cast<const float2*>(bds + 2048 + bi);
            float2 ba2 = *reinterpret_cast<const float2*>(bds + 4096 + bi);

            #pragma unroll
            for (int p = 0; p < 4; p++) {
                float bm = (p & 1) ? bm2.y : bm2.x;
                float bp = (p & 1) ? bp2.y : bp2.x;
                float ba = (p & 1) ? ba2.y : ba2.x;
                float xval = (p == 0) ? x0.x : (p == 1) ? x0.y : (p == 2) ? x1.x : x1.y;
                float m  = cm[p] + bm;
                float pv = cp_[p] + bp;
                float av = ca[p] + ba;
                float dd = xval - m;
                float tt = av + 0.5f * pv - 0.5f * __expf(pv) * dd * dd;
                s_t[p] += __expf(tt);
                s_a[p] += __expf(av);
            }
        }

        #pragma unroll
        for (int p = 0; p < 4; p++)
            part += __logf(s_t[p]) - __logf(s_a[p]);

        __syncthreads();   // all reads of curB done before it is refilled (dc+2)
    }

    // block reduce over 128 threads
    {
        __shared__ float red[4];
        #pragma unroll
        for (int o = 16; o > 0; o >>= 1) part += __shfl_down_sync(0xffffffffu, part, o);
        if (lane == 0) red[warp] = part;
        __syncthreads();
        if (tid == 0) {
            float s = red[0] + red[1] + red[2] + red[3];
            g_partC[blockIdx.x] = s;
        }
    }
}

// ---------------------------------------------------------------------------
// Final reduction: out = -( (PB + PC)/N + c2 ),  c2 = -0.5*D*log(2*pi)
// ---------------------------------------------------------------------------
__global__ __launch_bounds__(1024) void final_k(float* __restrict__ out)
{
    __shared__ float red[32];
    float s = 0.0f;
    const float4* pb = reinterpret_cast<const float4*>(g_partB);
    for (int i = threadIdx.x; i < NB_SAMP / 4; i += 1024) {
        float4 v = pb[i]; s += (v.x + v.y) + (v.z + v.w);
    }
    const float4* pc = reinterpret_cast<const float4*>(g_partC);
    for (int i = threadIdx.x; i < NB_DEC / 4; i += 1024) {
        float4 v = pc[i]; s += (v.x + v.y) + (v.z + v.w);
    }
    int lane = threadIdx.x & 31, wid = threadIdx.x >> 5;
    #pragma unroll
    for (int o = 16; o > 0; o >>= 1) s += __shfl_down_sync(0xffffffffu, s, o);
    if (lane == 0) red[wid] = s;
    __syncthreads();
    if (wid == 0) {
        s = red[lane];
        #pragma unroll
        for (int o = 16; o > 0; o >>= 1) s += __shfl_down_sync(0xffffffffu, s, o);
        if (lane == 0) {
            const float c2 = -0.5f * 256.0f * 1.8378770664093453f;
            out[0] = -(s / (float)N_ROWS + c2);
        }
    }
}

extern "C" void kernel_launch(void* const* d_in, const int* in_sizes, int n_in,
                              void* d_out, int out_size) {
    const float* x  = (const float*)d_in[0];
    const float* We = (const float*)d_in[1];
    const float* be = (const float*)d_in[2];
    const float* Wd = (const float*)d_in[3];
    const float* bd = (const float*)d_in[4];
    const float* ue = (const float*)d_in[5];
    const float* rr = (const float*)d_in[6];
    float* out = (float*)d_out;

    static bool attr_set = false;
    if (!attr_set) {
        cudaFuncSetAttribute(dec_k, cudaFuncAttributeMaxDynamicSharedMemorySize, 81920);
        attr_set = true;
    }

    prep_w<<<WT_N / 256, 256>>>(Wd);
    dim3 ge(ENC_OUT / 64, B_ROWS / 64);
    enc_gemm<<<ge, 256>>>(x, We, be);
    sample_k<<<NB_SAMP, 256>>>(ue, rr);
    dec_k<<<256, 128, 81920>>>(x, bd);
    final_k<<<1, 1024>>>(out);
}